// round 17
// baseline (speedup 1.0000x reference)
#include <cuda_runtime.h>
#include <cstddef>
#include <cstdint>

#define B_ 512
#define T_ 1024
#define U_ 128
#define RSTR 136   // padded h row stride in floats (128 data + 8 pad)

typedef unsigned long long ull;
typedef unsigned int uint;

// Allocation-free scratch (device global, .bss)
__device__ float g_pbuf[(size_t)T_ * B_ * U_];  // px1

// ---------- packed f32x2 helpers (Blackwell, PTX-only) ----------
__device__ __forceinline__ ull bc2(float v) {
    ull r; asm("mov.b64 %0, {%1,%1};" : "=l"(r) : "f"(v)); return r;
}
__device__ __forceinline__ ull pack2(float a, float b) {
    ull r; asm("mov.b64 %0, {%1,%2};" : "=l"(r) : "f"(a), "f"(b)); return r;
}
__device__ __forceinline__ void fma2(ull& d, ull a, ull b) {
    asm("fma.rn.f32x2 %0, %1, %2, %0;" : "+l"(d) : "l"(a), "l"(b));
}
__device__ __forceinline__ ull add2(ull a, ull b) {
    ull r; asm("add.rn.f32x2 %0, %1, %2;" : "=l"(r) : "l"(a), "l"(b)); return r;
}
__device__ __forceinline__ void unpk(ull v, float& lo, float& hi) {
    asm("mov.b64 {%0,%1}, %2;" : "=f"(lo), "=f"(hi) : "l"(v));
}

// h layout: the two ks slices' simultaneous 16B chunks are adjacent -> every
// broadcast LDS.128 is one wavefront.
//   k = ks*64 + half*32 + i*4 + m  ->  phys = half*64 + i*8 + ks*4 + m
__device__ __forceinline__ int hphys(int k) {
    return ((k >> 5) & 1) * 64 + ((k >> 2) & 7) * 8 + (k >> 6) * 4 + (k & 3);
}

// ============================================================================
// Parallel GEMM + bias (known-good since R4)
// ============================================================================
template <int KD, bool XLAY>
__global__ __launch_bounds__(256, 3)
void gemm_bias(const float* __restrict__ A, const float* __restrict__ W,
               const float* __restrict__ bias, float* __restrict__ out)
{
    extern __shared__ float sm[];
    float* Ws = sm;               // [KD][128]
    float* As = sm + KD * U_;     // [KD][68]
    const int tid  = threadIdx.x;
    const int row0 = blockIdx.x * 64;

    for (int i = tid; i < KD * U_; i += 256) Ws[i] = W[i];

    for (int i = tid; i < 64 * KD; i += 256) {
        int r = i / KD, k = i - r * KD;
        size_t off;
        if (XLAY) {
            int t = row0 >> 9;
            int b = (row0 & (B_ - 1)) + r;
            off = ((size_t)b * T_ + t) * KD + k;
        } else {
            off = (size_t)(row0 + r) * KD + k;
        }
        As[k * 68 + r] = A[off];
    }
    __syncthreads();

    const int u0 = (tid & 31) * 4;
    const int rb = (tid >> 5) * 8;

    ull acc[4][4];
#pragma unroll
    for (int a = 0; a < 4; a++)
#pragma unroll
        for (int b = 0; b < 4; b++) acc[a][b] = 0ULL;

#pragma unroll 4
    for (int k = 0; k < KD; k++) {
        ulonglong2 a01 = *(const ulonglong2*)(As + k * 68 + rb);
        ulonglong2 a23 = *(const ulonglong2*)(As + k * 68 + rb + 4);
        float4 w4 = *(const float4*)(Ws + k * U_ + u0);
        ull w;
        w = bc2(w4.x);
        fma2(acc[0][0], a01.x, w); fma2(acc[0][1], a01.y, w);
        fma2(acc[0][2], a23.x, w); fma2(acc[0][3], a23.y, w);
        w = bc2(w4.y);
        fma2(acc[1][0], a01.x, w); fma2(acc[1][1], a01.y, w);
        fma2(acc[1][2], a23.x, w); fma2(acc[1][3], a23.y, w);
        w = bc2(w4.z);
        fma2(acc[2][0], a01.x, w); fma2(acc[2][1], a01.y, w);
        fma2(acc[2][2], a23.x, w); fma2(acc[2][3], a23.y, w);
        w = bc2(w4.w);
        fma2(acc[3][0], a01.x, w); fma2(acc[3][1], a01.y, w);
        fma2(acc[3][2], a23.x, w); fma2(acc[3][3], a23.y, w);
    }

    float f[4][8];
#pragma unroll
    for (int uu = 0; uu < 4; uu++)
#pragma unroll
        for (int rp = 0; rp < 4; rp++) unpk(acc[uu][rp], f[uu][2 * rp], f[uu][2 * rp + 1]);

    float4 bv = *(const float4*)(bias + u0);
#pragma unroll
    for (int rr = 0; rr < 8; rr++) {
        float4 o = make_float4(f[0][rr] + bv.x, f[1][rr] + bv.y,
                               f[2][rr] + bv.z, f[3][rr] + bv.w);
        *(float4*)(out + (size_t)(row0 + rb + rr) * U_ + u0) = o;
    }
}

// ============================================================================
// recurBCD7: R12's proven geometry (256 thr = 128 units x 2 k-slices,
// 2 warps/SMSP, xor1 shfl fold, 1 barrier/step) with two serial-cost cuts:
//  (1) split the shared layer-2 accumulator into accQ (Wx2@h1) and accV
//      (Wh2@h2): dependency chain 64 -> 32 fma2 deep; merged by one add2
//      BEFORE the fold (fold count unchanged: 8).
//  (2) split the epilogue: ks==0 lane handles the h1 path (+p stream),
//      ks==1 lane handles the h2 path (+hfin). Symmetric fold leaves full
//      sums in both lanes, so this is free.
// ============================================================================
__global__ __launch_bounds__(256, 1)
void recurBCD7(const float* __restrict__ p,
               const float* __restrict__ Wh1c, const float* __restrict__ Wx2c,
               const float* __restrict__ b2c,  const float* __restrict__ Wh2c,
               const float* __restrict__ Wdc,  const float* __restrict__ bdc,
               float* __restrict__ dout)
{
    __shared__ __align__(16) float h1s[2][4 * RSTR];
    __shared__ __align__(16) float h2s[2][4 * RSTR];
    __shared__ float4 part_s[U_];

    const int tid = threadIdx.x;
    const int u   = tid >> 1;
    const int ks  = tid & 1;
    const int r0  = blockIdx.x * 4;

    // 3 x 32 packed k-pair weight columns (loaded once)
    ull wp[32], wq[32], wv[32];
#pragma unroll
    for (int i = 0; i < 32; i++) {
        int k = ks * 64 + 2 * i;
        wp[i] = pack2(Wh1c[(size_t)k * U_ + u], Wh1c[(size_t)(k + 1) * U_ + u]);
        wq[i] = pack2(Wx2c[(size_t)k * U_ + u], Wx2c[(size_t)(k + 1) * U_ + u]);
        wv[i] = pack2(Wh2c[(size_t)k * U_ + u], Wh2c[(size_t)(k + 1) * U_ + u]);
    }
    const float b2v = b2c[u];

    for (int i = tid; i < 4 * RSTR; i += 256) {
        h1s[0][i] = 0.f; h1s[1][i] = 0.f;
        h2s[0][i] = 0.f; h2s[1][i] = 0.f;
    }

    const int physu = hphys(u);
    const float* prow = p + (size_t)r0 * U_ + u;
    float pv[4] = {0.f, 0.f, 0.f, 0.f};
    if (ks == 0) { pv[0] = prow[0]; pv[1] = prow[U_]; pv[2] = prow[2 * U_]; pv[3] = prow[3 * U_]; }
    float hfin[4] = {0.f, 0.f, 0.f, 0.f};   // tracked by ks==1 lanes
    __syncthreads();

    for (int t = 0; t <= T_; t++) {
        float pn[4] = {0.f, 0.f, 0.f, 0.f};
        if (ks == 0) {
            int tn = (t < T_ - 1) ? t + 1 : T_ - 1;
            const float* pp = prow + (size_t)tn * B_ * U_;
            pn[0] = pp[0]; pn[1] = pp[U_]; pn[2] = pp[2 * U_]; pn[3] = pp[3 * U_];
        }

        const float* hb1 = h1s[t & 1];        // h1_{t-1}
        float*       hn1 = h1s[(t + 1) & 1];
        const float* hb2 = h2s[t & 1];        // h2_{t-2}
        float*       hn2 = h2s[(t + 1) & 1];

        ull acc[4]  = {0ULL, 0ULL, 0ULL, 0ULL};   // Wh1 @ h1
        ull accQ[4] = {0ULL, 0ULL, 0ULL, 0ULL};   // Wx2 @ h1
        ull accV[4] = {0ULL, 0ULL, 0ULL, 0ULL};   // Wh2 @ h2
#pragma unroll
        for (int r = 0; r < 4; r++) {
            const float* rb1 = hb1 + r * RSTR + ks * 4;
            const float* rb2 = hb2 + r * RSTR + ks * 4;
#pragma unroll
            for (int half = 0; half < 2; half++) {
#pragma unroll
                for (int i = 0; i < 8; i++) {
                    int wi = half * 16 + 2 * i;
                    ulonglong2 hv = *(const ulonglong2*)(rb1 + half * 64 + i * 8);
                    fma2(acc[r],  hv.x, wp[wi]);
                    fma2(acc[r],  hv.y, wp[wi + 1]);
                    fma2(accQ[r], hv.x, wq[wi]);
                    fma2(accQ[r], hv.y, wq[wi + 1]);
                    ulonglong2 gv = *(const ulonglong2*)(rb2 + half * 64 + i * 8);
                    fma2(accV[r], gv.x, wv[wi]);
                    fma2(accV[r], gv.y, wv[wi + 1]);
                }
            }
        }

        // merge Q+V before fold (keeps fold count at 8), then xor1 fold
        float s1[4], s2[4];
#pragma unroll
        for (int r = 0; r < 4; r++) {
            uint lo = (uint)acc[r], hi = (uint)(acc[r] >> 32);
            uint plo = __shfl_xor_sync(0xffffffffu, lo, 1);
            uint phi = __shfl_xor_sync(0xffffffffu, hi, 1);
            s1[r] = __uint_as_float(lo) + __uint_as_float(plo)
                  + __uint_as_float(hi) + __uint_as_float(phi);

            ull bsum = add2(accQ[r], accV[r]);
            uint blo = (uint)bsum, bhi = (uint)(bsum >> 32);
            uint pblo = __shfl_xor_sync(0xffffffffu, blo, 1);
            uint pbhi = __shfl_xor_sync(0xffffffffu, bhi, 1);
            s2[r] = __uint_as_float(blo) + __uint_as_float(pblo)
                  + __uint_as_float(bhi) + __uint_as_float(pbhi);
        }

        // split epilogue: ks==0 -> h1 path, ks==1 -> h2 path
        if (ks == 0) {
            if (t < T_) {
#pragma unroll
                for (int r = 0; r < 4; r++) {
                    hn1[r * RSTR + physu] = fmaxf(s1[r] + pv[r], 0.f);
                    pv[r] = pn[r];
                }
            }
        } else {
            if (t >= 1) {                      // h2_{t-1}
#pragma unroll
                for (int r = 0; r < 4; r++) {
                    hfin[r] = fmaxf(s2[r] + b2v, 0.f);
                    hn2[r * RSTR + physu] = hfin[r];
                }
            }
        }
        __syncthreads();
    }

    // final projection: ks==1 lanes hold h2_{T-1}(4 rows, unit u)
    if (ks == 1) {
        float wd = Wdc[u];
        part_s[u] = make_float4(hfin[0] * wd, hfin[1] * wd, hfin[2] * wd, hfin[3] * wd);
    }
    __syncthreads();
    if (tid < 4) {
        float ssum = 0.f;
        for (int i = 0; i < U_; i++) ssum += ((const float*)(part_s + i))[tid];
        dout[r0 + tid] = ssum + bdc[0];
    }
}

// ============================================================================
extern "C" void kernel_launch(void* const* d_in, const int* in_sizes, int n_in,
                              void* d_out, int out_size)
{
    (void)in_sizes; (void)n_in; (void)out_size;
    const float* x   = (const float*)d_in[0];
    const float* Wx1 = (const float*)d_in[1];
    const float* Wh1 = (const float*)d_in[2];
    const float* b1  = (const float*)d_in[3];
    const float* Wx2 = (const float*)d_in[4];
    const float* Wh2 = (const float*)d_in[5];
    const float* b2  = (const float*)d_in[6];
    const float* Wd  = (const float*)d_in[7];
    const float* bd  = (const float*)d_in[8];
    float* out = (float*)d_out;

    float* pbuf;
    cudaGetSymbolAddress((void**)&pbuf, g_pbuf);

    const int ngrid = (T_ * B_) / 64;                        // 8192 tiles
    const int smemA = (64 * U_ + 64 * 68) * sizeof(float);   // 50176 B
    cudaFuncSetAttribute(gemm_bias<64, true>,
                         cudaFuncAttributeMaxDynamicSharedMemorySize, smemA);

    // Phase A: px1 = x @ Wx1 + b1           (layout [t][b][u])
    gemm_bias<64, true><<<ngrid, 256, smemA>>>(x, Wx1, b1, pbuf);
    // Phases B+C+D fused (split accumulators + split epilogue)
    recurBCD7<<<B_ / 4, 256>>>(pbuf, Wh1, Wx2, b2, Wh2, Wd, bd, out);
}